// round 2
// baseline (speedup 1.0000x reference)
#include <cuda_runtime.h>
#include <cuda_bf16.h>

#define N_ATOMS 50000
#define N_BONDS 100000
#define NE      (2 * N_BONDS)       // 200000 directed edges
#define HIDDEN  300
#define ATOM_DIM 133
#define BOND_DIM 14
#define N_MOL   2048
#define FEAT_DIM 200
#define DEPTH   3
#define OUT_COLS (HIDDEN + FEAT_DIM)  // 500

// ---------------- scratch (device globals; no allocation allowed) ----------
__device__ float g_h0 [(size_t)NE * HIDDEN];        // 240 MB
__device__ float g_hA [(size_t)NE * HIDDEN];        // 240 MB
__device__ float g_hB [(size_t)NE * HIDDEN];        // 240 MB
__device__ float g_inc[(size_t)N_ATOMS * HIDDEN];   // 60 MB (also reused as m_v)

// ---------------------------------------------------------------------------
// Generic fused GEMM:  out[r, 0:300] = relu( A(r,:) @ W + bias (+ resid[r,:]) )
// A is assembled on the fly per mode:
//   mode 0: A(r,k) = k<14  ? edge_attr[r*14+k] : x[src[r]*133 + k-14]        (K=147)
//   mode 2: A(r,k) = k<133 ? x[r*133+k]        : m_v[r*300 + k-133]          (K=433)
//   mode 3: A(r,k) = inc[src[r]*300+k] - h[rev[r]*300+k]                     (K=300)
// Tiling: BM=64, BN=64, BK=16, 256 threads, 4x4 microtile.
// ---------------------------------------------------------------------------
__global__ void gemm_fused(int mode, int rows, int K,
                           const float* __restrict__ G0,   // m0: edge_attr | m2: x   | m3: inc
                           const float* __restrict__ G1,   // m0: x         | m2: m_v | m3: h
                           const int*   __restrict__ gidx, // m0: src       | m3: src
                           const int*   __restrict__ gidx2,// m3: rev
                           const float* __restrict__ W,    // [K, 300]
                           const float* __restrict__ bias, // [300]
                           const float* __restrict__ resid,// [rows, 300] or null
                           float* __restrict__ out)        // [rows, 300]
{
    __shared__ float As[64][17];   // padded
    __shared__ float Bs[16][64];

    const int tid = threadIdx.x;
    const int m0 = blockIdx.x * 64;
    const int n0 = blockIdx.y * 64;
    const int ty = tid >> 4;       // 0..15
    const int tx = tid & 15;       // 0..15

    float acc[4][4];
#pragma unroll
    for (int i = 0; i < 4; i++)
#pragma unroll
        for (int j = 0; j < 4; j++) acc[i][j] = 0.f;

    for (int k0 = 0; k0 < K; k0 += 16) {
        // ---- load A tile: 64x16 = 1024 elems, 4 per thread, contiguous in k
#pragma unroll
        for (int i = 0; i < 4; i++) {
            int li = tid + i * 256;
            int r  = li >> 4;          // 0..63
            int k  = li & 15;
            int row = m0 + r;
            int kg  = k0 + k;
            float v = 0.f;
            if (row < rows && kg < K) {
                if (mode == 3) {
                    int s  = gidx[row];
                    int rv = gidx2[row];
                    v = G0[(size_t)s  * HIDDEN + kg]
                      - G1[(size_t)rv * HIDDEN + kg];
                } else if (mode == 0) {
                    if (kg < BOND_DIM) v = G0[row * BOND_DIM + kg];
                    else {
                        int s = gidx[row];
                        v = G1[(size_t)s * ATOM_DIM + (kg - BOND_DIM)];
                    }
                } else { // mode 2
                    if (kg < ATOM_DIM) v = G0[(size_t)row * ATOM_DIM + kg];
                    else               v = G1[(size_t)row * HIDDEN + (kg - ATOM_DIM)];
                }
            }
            As[r][k] = v;
        }
        // ---- load B tile: 16x64 = 1024 elems, contiguous in n
#pragma unroll
        for (int i = 0; i < 4; i++) {
            int li = tid + i * 256;
            int k  = li >> 6;          // 0..15
            int n  = li & 63;
            int kg = k0 + k;
            int ng = n0 + n;
            float v = 0.f;
            if (kg < K && ng < HIDDEN) v = W[(size_t)kg * HIDDEN + ng];
            Bs[k][n] = v;
        }
        __syncthreads();

#pragma unroll
        for (int kk = 0; kk < 16; kk++) {
            float a[4], b[4];
#pragma unroll
            for (int i = 0; i < 4; i++) a[i] = As[ty * 4 + i][kk];
            float4 bv = *(const float4*)&Bs[kk][tx * 4];
            b[0] = bv.x; b[1] = bv.y; b[2] = bv.z; b[3] = bv.w;
#pragma unroll
            for (int i = 0; i < 4; i++)
#pragma unroll
                for (int j = 0; j < 4; j++)
                    acc[i][j] = fmaf(a[i], b[j], acc[i][j]);
        }
        __syncthreads();
    }

    // ---- epilogue: bias (+resid) + relu
#pragma unroll
    for (int i = 0; i < 4; i++) {
        int row = m0 + ty * 4 + i;
        if (row >= rows) continue;
#pragma unroll
        for (int j = 0; j < 4; j++) {
            int col = n0 + tx * 4 + j;
            if (col >= HIDDEN) continue;
            float v = acc[i][j] + bias[col];
            if (resid) v += resid[(size_t)row * HIDDEN + col];
            out[(size_t)row * HIDDEN + col] = v > 0.f ? v : 0.f;
        }
    }
}

// ---------------------------------------------------------------------------
// Segment sum: acc[idx[e], :] += h[e, :]    (acc pre-zeroed)
// one thread per (row, float4-chunk); 75 chunks of 4 cols = 300
// ---------------------------------------------------------------------------
__global__ void scatter_add(const float* __restrict__ h,
                            const int*   __restrict__ idx,
                            float* __restrict__ acc, int rows)
{
    int gid = blockIdx.x * blockDim.x + threadIdx.x;
    if (gid >= rows * 75) return;
    int e = gid / 75;
    int q = gid % 75;
    float4 v = ((const float4*)h)[(size_t)e * 75 + q];
    int d = idx[e];
    float* p = acc + (size_t)d * HIDDEN + q * 4;
    atomicAdd(p + 0, v.x);
    atomicAdd(p + 1, v.y);
    atomicAdd(p + 2, v.z);
    atomicAdd(p + 3, v.w);
}

// out[mol, 0:300] = 0 ; out[mol, 300:500] = features[mol, :]
__global__ void init_out(float* __restrict__ out, const float* __restrict__ feat)
{
    int gid = blockIdx.x * blockDim.x + threadIdx.x;
    if (gid >= N_MOL * OUT_COLS) return;
    int mol = gid / OUT_COLS;
    int c   = gid % OUT_COLS;
    out[gid] = (c < HIDDEN) ? 0.f : feat[mol * FEAT_DIM + (c - HIDDEN)];
}

// out[mol_id[v], j] += h_v[v, j]
__global__ void readout(const float* __restrict__ hv,
                        const int* __restrict__ mol_id,
                        float* __restrict__ out)
{
    int gid = blockIdx.x * blockDim.x + threadIdx.x;
    if (gid >= N_ATOMS * 75) return;
    int v = gid / 75;
    int q = gid % 75;
    float4 x = ((const float4*)hv)[(size_t)v * 75 + q];
    int mol = mol_id[v];
    float* p = out + (size_t)mol * OUT_COLS + q * 4;
    atomicAdd(p + 0, x.x);
    atomicAdd(p + 1, x.y);
    atomicAdd(p + 2, x.z);
    atomicAdd(p + 3, x.w);
}

// ---------------------------------------------------------------------------
extern "C" void kernel_launch(void* const* d_in, const int* in_sizes, int n_in,
                              void* d_out, int out_size)
{
    const float* x         = (const float*)d_in[0];
    const float* edge_attr = (const float*)d_in[1];
    const int*   edge_src  = (const int*)  d_in[2];
    const int*   edge_dst  = (const int*)  d_in[3];
    const int*   b2rev     = (const int*)  d_in[4];
    const int*   mol_id    = (const int*)  d_in[5];
    const float* features  = (const float*)d_in[6];
    const float* Wi        = (const float*)d_in[7];
    const float* bi        = (const float*)d_in[8];
    const float* Wm        = (const float*)d_in[9];
    const float* bm        = (const float*)d_in[10];
    const float* Wa        = (const float*)d_in[11];
    const float* ba        = (const float*)d_in[12];
    float* out = (float*)d_out;

    float *h0, *hA, *hB, *inc;
    cudaGetSymbolAddress((void**)&h0,  g_h0);
    cudaGetSymbolAddress((void**)&hA,  g_hA);
    cudaGetSymbolAddress((void**)&hB,  g_hB);
    cudaGetSymbolAddress((void**)&inc, g_inc);

    dim3 blk(256);
    dim3 gemm_grid_E((NE + 63) / 64, (HIDDEN + 63) / 64);
    dim3 gemm_grid_V((N_ATOMS + 63) / 64, (HIDDEN + 63) / 64);
    int scatE = (NE * 75 + 255) / 256;
    int scatV = (N_ATOMS * 75 + 255) / 256;

    // h0 = relu([edge_attr, x[src]] @ Wi + bi)
    gemm_fused<<<gemm_grid_E, blk>>>(0, NE, BOND_DIM + ATOM_DIM,
                                     edge_attr, x, edge_src, nullptr,
                                     Wi, bi, nullptr, h0);

    const float* hin = h0;
    float* houts[3] = { hA, hB, hA };
    for (int it = 0; it < DEPTH; it++) {
        float* hout = houts[it];
        cudaMemsetAsync(inc, 0, (size_t)N_ATOMS * HIDDEN * sizeof(float));
        scatter_add<<<scatE, blk>>>(hin, edge_dst, inc, NE);
        // h = relu(h0 + (inc[src] - h[rev]) @ Wm + bm), A assembled in-kernel
        gemm_fused<<<gemm_grid_E, blk>>>(3, NE, HIDDEN,
                                         inc, hin, edge_src, b2rev,
                                         Wm, bm, h0, hout);
        hin = hout;
    }

    // m_v = segment_sum(h over edge_src) — reuse inc buffer
    cudaMemsetAsync(inc, 0, (size_t)N_ATOMS * HIDDEN * sizeof(float));
    scatter_add<<<scatE, blk>>>(hin, edge_src, inc, NE);

    // h_v = relu([x, m_v] @ Wa + ba) -> reuse hB
    gemm_fused<<<gemm_grid_V, blk>>>(2, N_ATOMS, ATOM_DIM + HIDDEN,
                                     x, inc, nullptr, nullptr,
                                     Wa, ba, nullptr, hB);

    // output: zeros | features, then molecule-sum readout
    init_out<<<(N_MOL * OUT_COLS + 255) / 256, blk>>>(out, features);
    readout<<<scatV, blk>>>(hB, mol_id, out);
}